// round 2
// baseline (speedup 1.0000x reference)
#include <cuda_runtime.h>
#include <cuda_bf16.h>

// ---------------------------------------------------------------------------
// Model_70222715289880: bilinear score -> top-k(10/64) -> gather of 10 tensors
//
// B=8, K=64, TOPK=10, N_R=4, L_R=128, H=512, D=128, D2 = 640.
//
// Output = concat(flatten(...)) as float32 in reference tuple order:
//   0              80         topk_scores
//   80             163840     topk_s_r
//   163920         20971520   topk_h_r
//   21135440       40960      topk_r_a
//   21176400       40960      topk_r_o
//   21217360       320        topk_r_o_mask
//   21217680       10240      topk_rev_batch (int->float)
//   21227920       10240      topk_rev_mask
//   21238160       80         topk_ratings (int->float)
//   21238240       10240      topk_rev_extend_vocab (int->float)
//   21248480       80         idx (int->float)
// ---------------------------------------------------------------------------

#define Bq   8
#define Kk   64
#define TOPK 10
#define D2   640

#define OFF_SCORES   0
#define OFF_RATINGS  21238160
#define OFF_IDX      21248480

// vec4 (float4) offsets of gathered segments in dst
#define V4_SR    20u
#define V4_HR    40980u
#define V4_RA    5283860u
#define V4_RO    5294100u
#define V4_MASK  5304340u
#define V4_RB    5304420u
#define V4_RM    5306980u
#define V4_RE    5309560u

// gather-index (g) range boundaries, in vec4 units
#define G_SR_END   40960u
#define G_HR_END   5283840u
#define G_RA_END   5294080u
#define G_RO_END   5304320u
#define G_MK_END   5304400u
#define G_RB_END   5306960u
#define G_RM_END   5309520u
#define G_RE_END   5312080u
#define G_TOTAL    5312080u

__device__ int g_topk_idx[Bq * TOPK];

// ---------------------------------------------------------------------------
// XLA's tanh (elemental_ir_emitter::EmitTanh == Eigen generic_fast_tanh_float):
// clamp to ±7.90531110763549805, rational Horner, linear for |x| < 0.0004.
// Written with explicit fmaf to match the FFMA-contracted code XLA emits.
// The *exact* plateau structure of this function (which inputs round to the
// same float near saturation) is what determines the reference's top-k tie
// set — libdevice tanhf has a different saturation threshold and does NOT
// reproduce it.
// ---------------------------------------------------------------------------
__device__ __forceinline__ float xla_tanhf(float x)
{
    const float kClamp = 7.90531110763549805f;
    float xc = fmaxf(-kClamp, fminf(x, kClamp));
    float x2 = xc * xc;

    float p = fmaf(x2, -2.76076847742355e-16f, 2.00018790482477e-13f);
    p = fmaf(x2, p, -8.60467152213735e-11f);
    p = fmaf(x2, p,  5.12229709037114e-08f);
    p = fmaf(x2, p,  1.48572235717979e-05f);
    p = fmaf(x2, p,  6.37261928875436e-04f);
    p = fmaf(x2, p,  4.89352455891786e-03f);
    p = xc * p;

    float q = fmaf(x2, 1.19825839466702e-06f, 1.18534705686654e-04f);
    q = fmaf(x2, q, 2.26843463243900e-03f);
    q = fmaf(x2, q, 4.89352518554385e-03f);

    float r = p / q;
    return (fabsf(x) < 0.0004f) ? x : r;
}

// ---------------------------------------------------------------------------
// Kernel 1: scores = xla_tanh(a_s_q @ W @ a_s_r^T), top-10, small outputs
// ---------------------------------------------------------------------------
__global__ __launch_bounds__(256) void score_topk_kernel(
    const float* __restrict__ a_s_q,
    const float* __restrict__ a_s_r,
    const float* __restrict__ W,
    const int*   __restrict__ ratings,
    float* __restrict__ out)
{
    __shared__ float aq[D2];
    __shared__ float q[D2];
    __shared__ float sc[Kk];

    const int b = blockIdx.x;
    const int tid = threadIdx.x;

    for (int i = tid; i < D2; i += 256) aq[i] = a_s_q[b * D2 + i];
    __syncthreads();

    for (int e = tid; e < D2; e += 256) {
        float s = 0.f;
        #pragma unroll 8
        for (int d = 0; d < D2; ++d) s = fmaf(aq[d], W[d * D2 + e], s);
        q[e] = s;
    }
    __syncthreads();

    // 4 threads per k
    {
        const int k = tid >> 2;
        const int sub = tid & 3;
        const float* ar = a_s_r + ((size_t)(b * Kk + k)) * D2;
        float s = 0.f;
        for (int e = sub; e < D2; e += 4) s = fmaf(q[e], ar[e], s);
        s += __shfl_xor_sync(0xFFFFFFFFu, s, 1);
        s += __shfl_xor_sync(0xFFFFFFFFu, s, 2);
        if (sub == 0) sc[k] = xla_tanhf(s);
    }
    __syncthreads();

    if (tid == 0) {
        bool used[Kk];
        #pragma unroll
        for (int k = 0; k < Kk; ++k) used[k] = false;
        #pragma unroll
        for (int t = 0; t < TOPK; ++t) {
            int best = 0;
            float bv = -2e30f;
            for (int k = 0; k < Kk; ++k) {
                // strict >: among exact ties, lowest index wins (lax.top_k)
                if (!used[k] && sc[k] > bv) { bv = sc[k]; best = k; }
            }
            used[best] = true;
            g_topk_idx[b * TOPK + t] = best;
            out[OFF_SCORES  + b * TOPK + t] = bv;
            out[OFF_RATINGS + b * TOPK + t] = (float)ratings[b * Kk + best];
            out[OFF_IDX     + b * TOPK + t] = (float)best;
        }
    }
}

// ---------------------------------------------------------------------------
// Kernel 2: fused vectorized gather of all array segments
// ---------------------------------------------------------------------------
__global__ __launch_bounds__(256) void gather_kernel(
    const float4* __restrict__ s_r,
    const float4* __restrict__ h_r,
    const float4* __restrict__ r_a,
    const float4* __restrict__ r_o,
    const float4* __restrict__ mask,
    const int4*   __restrict__ rb,
    const float4* __restrict__ rm,
    const int4*   __restrict__ re,
    float4* __restrict__ out4)
{
    __shared__ int idx_s[Bq * TOPK];
    if (threadIdx.x < Bq * TOPK) idx_s[threadIdx.x] = g_topk_idx[threadIdx.x];
    __syncthreads();

    const unsigned stride = gridDim.x * blockDim.x;
    for (unsigned g = blockIdx.x * blockDim.x + threadIdx.x; g < G_TOTAL; g += stride) {
        if (g >= G_SR_END && g < G_HR_END) {
            // h_r: 98.7% of traffic, inner = 65536 v4 -> shifts/masks only
            const unsigned local = g - G_SR_END;
            const unsigned row = local >> 16;
            const unsigned iv  = local & 0xFFFFu;
            const unsigned b   = row / TOPK;
            const unsigned k   = (unsigned)idx_s[row];
            out4[V4_HR + local] = h_r[(b * Kk + k) * 65536u + iv];
        } else if (g < G_SR_END) {
            const unsigned row = g >> 9;
            const unsigned iv  = g & 511u;
            const unsigned b   = row / TOPK;
            const unsigned k   = (unsigned)idx_s[row];
            out4[V4_SR + g] = s_r[(b * Kk + k) * 512u + iv];
        } else if (g < G_RA_END) {
            const unsigned local = g - G_HR_END;
            const unsigned row = local >> 7;
            const unsigned iv  = local & 127u;
            const unsigned b   = row / TOPK;
            const unsigned k   = (unsigned)idx_s[row];
            out4[V4_RA + local] = r_a[(b * Kk + k) * 128u + iv];
        } else if (g < G_RO_END) {
            const unsigned local = g - G_RA_END;
            const unsigned row = local >> 7;
            const unsigned iv  = local & 127u;
            const unsigned b   = row / TOPK;
            const unsigned k   = (unsigned)idx_s[row];
            out4[V4_RO + local] = r_o[(b * Kk + k) * 128u + iv];
        } else if (g < G_MK_END) {
            const unsigned local = g - G_RO_END;
            const unsigned b = local / TOPK;
            const unsigned k = (unsigned)idx_s[local];
            out4[V4_MASK + local] = mask[b * Kk + k];
        } else if (g < G_RB_END) {
            const unsigned local = g - G_MK_END;
            const unsigned row = local >> 5;
            const unsigned iv  = local & 31u;
            const unsigned b   = row / TOPK;
            const unsigned k   = (unsigned)idx_s[row];
            const int4 v = rb[(b * Kk + k) * 32u + iv];
            out4[V4_RB + local] = make_float4((float)v.x, (float)v.y, (float)v.z, (float)v.w);
        } else if (g < G_RM_END) {
            const unsigned local = g - G_RB_END;
            const unsigned row = local >> 5;
            const unsigned iv  = local & 31u;
            const unsigned b   = row / TOPK;
            const unsigned k   = (unsigned)idx_s[row];
            out4[V4_RM + local] = rm[(b * Kk + k) * 32u + iv];
        } else {
            const unsigned local = g - G_RM_END;
            const unsigned row = local >> 5;
            const unsigned iv  = local & 31u;
            const unsigned b   = row / TOPK;
            const unsigned k   = (unsigned)idx_s[row];
            const int4 v = re[(b * Kk + k) * 32u + iv];
            out4[V4_RE + local] = make_float4((float)v.x, (float)v.y, (float)v.z, (float)v.w);
        }
    }
}

// ---------------------------------------------------------------------------
extern "C" void kernel_launch(void* const* d_in, const int* in_sizes, int n_in,
                              void* d_out, int out_size)
{
    const float* a_s_q   = (const float*)d_in[0];
    const float* a_s_r   = (const float*)d_in[1];
    const float* W       = (const float*)d_in[2];
    const float* s_r     = (const float*)d_in[3];
    const float* h_r     = (const float*)d_in[4];
    const float* r_a     = (const float*)d_in[5];
    const float* r_o     = (const float*)d_in[6];
    const float* mask    = (const float*)d_in[7];
    const int*   rb      = (const int*)d_in[8];
    const float* rm      = (const float*)d_in[9];
    const int*   ratings = (const int*)d_in[10];
    const int*   re      = (const int*)d_in[11];
    float* out = (float*)d_out;

    score_topk_kernel<<<Bq, 256>>>(a_s_q, a_s_r, W, ratings, out);

    gather_kernel<<<4736, 256>>>(
        (const float4*)s_r, (const float4*)h_r, (const float4*)r_a,
        (const float4*)r_o, (const float4*)mask, (const int4*)rb,
        (const float4*)rm, (const int4*)re, (float4*)out);
}